// round 15
// baseline (speedup 1.0000x reference)
#include <cuda_runtime.h>
#include <cuda_fp16.h>
#include <cstdint>

// Problem shape (fixed)
#define MDIM 4096
#define KDIM 4096
#define BDIM 4
#define NB   2048
#define NTOT (BDIM * NB)   // 8192

// GEMM tiling: 128x128x64, 256 threads, 3 stages, 2 CTAs/SM (R6 winner)
#define BM 128
#define BN 128
#define BK 64              // 64 fp16 = 128B row
#define STAGES 3
#define NKT (KDIM / BK)    // 64
#define THREADS 256

#define A_SZ (BM * BK * 2)             // 16384 B
#define B_SZ (BN * BK * 2)             // 16384 B
#define STAGE_SZ (A_SZ + B_SZ)         // 32768 B
#define SMEM_TOTAL (STAGES * STAGE_SZ) // 98304 B -> 2 CTAs/SM

// SW128-style swizzle for 128B rows (XOR bits[6:4] with bits[9:7])
#define SW(o) ((o) ^ (((o) >> 3) & 0x70))

// Scratch (device globals — no allocation allowed)
__device__ __align__(1024) __half g_Wh[(size_t)MDIM * KDIM];   // 33.5 MB dense W fp16
__device__ __align__(1024) __half g_xh[(size_t)NTOT * KDIM];   // 67 MB x fp16

// ---------------------------------------------------------------------------
// PTX helpers (baseline sm_80/sm_90 features only)
// ---------------------------------------------------------------------------
__device__ __forceinline__ uint32_t smem_u32(const void* p) {
    uint32_t a;
    asm("{ .reg .u64 t; cvta.to.shared.u64 t, %1; cvt.u32.u64 %0, t; }"
        : "=r"(a) : "l"(p));
    return a;
}

__device__ __forceinline__ void cp_async16(uint32_t dst, const void* src) {
    asm volatile("cp.async.cg.shared.global [%0], [%1], 16;"
                 :: "r"(dst), "l"(src) : "memory");
}
#define CP_COMMIT() asm volatile("cp.async.commit_group;" ::: "memory")
#define CP_WAIT(n)  asm volatile("cp.async.wait_group %0;" :: "n"(n) : "memory")

#define LDSM_X4(R, addr) \
    asm volatile("ldmatrix.sync.aligned.m8n8.x4.shared.b16 {%0,%1,%2,%3}, [%4];" \
                 : "=r"((R)[0]), "=r"((R)[1]), "=r"((R)[2]), "=r"((R)[3]) \
                 : "r"(addr))

#define MMA16816(d, a, b0, b1) \
    asm volatile("mma.sync.aligned.m16n8k16.row.col.f32.f16.f16.f32 " \
                 "{%0,%1,%2,%3}, {%4,%5,%6,%7}, {%8,%9}, {%0,%1,%2,%3};" \
                 : "+f"((d)[0]), "+f"((d)[1]), "+f"((d)[2]), "+f"((d)[3]) \
                 : "r"((a)[0]), "r"((a)[1]), "r"((a)[2]), "r"((a)[3]), \
                   "r"(b0), "r"(b1))

// ---------------------------------------------------------------------------
// Kernel 1: fused zero + CSR->dense fp16 scatter. One CTA per W row.
// Zero the row (uint4), barrier, then deterministic run-head scatter
// (cols sorted per row; duplicate runs adjacent — head sums the run in fp32).
// ---------------------------------------------------------------------------
__global__ void scatter_fused_kernel(const float* __restrict__ vals,
                                     const int* __restrict__ ci,
                                     int per_row) {
    const int row = blockIdx.x;
    uint4 z = make_uint4(0, 0, 0, 0);
    uint4* wr = reinterpret_cast<uint4*>(g_Wh + (size_t)row * KDIM);
    #pragma unroll
    for (int i = 0; i < 2; i++)
        wr[threadIdx.x + i * 256] = z;
    __syncthreads();

    const int rs = row * per_row;
    const int re = rs + per_row;
    for (int j = threadIdx.x; j < per_row; j += blockDim.x) {
        int g = rs + j;
        int c = ci[g];
        if (j > 0 && ci[g - 1] == c) continue;   // not run head
        float s = vals[g];
        int t = g + 1;
        while (t < re && ci[t] == c) { s += vals[t]; t++; }
        g_Wh[(size_t)row * KDIM + c] = __float2half_rn(s);
    }
}

// ---------------------------------------------------------------------------
// Kernel 2: x fp32 -> fp16 (8 floats / thread, 16B stores)
// ---------------------------------------------------------------------------
__global__ void convert_x_kernel(const float4* __restrict__ x) {
    size_t i = (size_t)blockIdx.x * blockDim.x + threadIdx.x;
    float4 a = x[2 * i];
    float4 b = x[2 * i + 1];
    __half2 h0 = __floats2half2_rn(a.x, a.y);
    __half2 h1 = __floats2half2_rn(a.z, a.w);
    __half2 h2 = __floats2half2_rn(b.x, b.y);
    __half2 h3 = __floats2half2_rn(b.z, b.w);
    uint4 o;
    o.x = *reinterpret_cast<uint32_t*>(&h0);
    o.y = *reinterpret_cast<uint32_t*>(&h1);
    o.z = *reinterpret_cast<uint32_t*>(&h2);
    o.w = *reinterpret_cast<uint32_t*>(&h3);
    reinterpret_cast<uint4*>(g_xh)[i] = o;
}

// ---------------------------------------------------------------------------
// Kernel 3: fp16 GEMM via mma.sync (HMMA), 128x128x64 tiles, 3-stage cp.async,
// 2 CTAs/SM, kt-loop unrolled by STAGES for static stage addressing.
// (R6-proven mainloop — all loads .cg.)
// C[m, gn] = sum_k Wh[m,k] * xh[gn,k]
// ---------------------------------------------------------------------------
__global__ __launch_bounds__(THREADS, 2)
void gemm_kernel(float* __restrict__ out) {
    extern __shared__ __align__(1024) char smem[];
    const uint32_t sb = smem_u32(smem);
    const int tid = threadIdx.x;
    const int wid = tid >> 5;
    const int lane = tid & 31;

    const int n0 = blockIdx.x * BN;       // n within batch
    const int m0 = blockIdx.y * BM;
    const int b  = blockIdx.z;

    const __half* gA = g_Wh + (size_t)m0 * KDIM;                 // [BM, K]
    const __half* gB = g_xh + ((size_t)b * NB + n0) * KDIM;      // [BN, K]

    // warp layout: 2 (m) x 4 (n); warp tile 64 x 32
    const int wm = (wid & 1) * 64;
    const int wn = (wid >> 1) * 32;

    float acc[4][4][4];
    #pragma unroll
    for (int i = 0; i < 4; i++)
        #pragma unroll
        for (int j = 0; j < 4; j++)
            #pragma unroll
            for (int q = 0; q < 4; q++) acc[i][j][q] = 0.f;

    // loader thread's fixed chunk coords (row r, 16B-chunk cc within 128B row)
    const int ld_r0 = tid >> 3;          // rows 0..31 (+32 per j)
    const int ld_cc = (tid & 7) * 16;    // byte offset of 16B chunk

    #define ISSUE_STAGE(S, KT)                                                  \
    {                                                                           \
        const uint32_t sA_ = sb + (S) * STAGE_SZ;                               \
        const uint32_t sB_ = sA_ + A_SZ;                                        \
        const __half* ga_ = gA + (KT) * BK;                                     \
        const __half* gb_ = gB + (KT) * BK;                                     \
        _Pragma("unroll")                                                       \
        for (int j = 0; j < 4; j++) {                                           \
            int r = ld_r0 + j * 32;                                             \
            cp_async16(sA_ + SW(r * 128 + ld_cc),                               \
                       ga_ + (size_t)r * KDIM + (ld_cc >> 1));                  \
            cp_async16(sB_ + SW(r * 128 + ld_cc),                               \
                       gb_ + (size_t)r * KDIM + (ld_cc >> 1));                  \
        }                                                                       \
    }

    // ldmatrix lane address components
    const int a_row_lane = lane & 15;                       // A: row within m16
    const int a_col_lane = (lane >> 4) << 4;                // A: 0 or 16 bytes
    const int b_row_lane = ((lane >> 4) << 3) + (lane & 7); // B: row within n16
    const int b_col_lane = ((lane >> 3) & 1) << 4;          // B: 0 or 16 bytes

    #define KT_BODY(S, KT)                                                      \
    {                                                                           \
        CP_WAIT(STAGES - 2);                                                    \
        __syncthreads();                                                        \
        if ((KT) + STAGES - 1 < NKT) ISSUE_STAGE(((S) + STAGES - 1) % STAGES,   \
                                                 (KT) + STAGES - 1);            \
        CP_COMMIT();                                                            \
        const uint32_t sA = sb + (S) * STAGE_SZ;                                \
        const uint32_t sB = sA + A_SZ;                                          \
        _Pragma("unroll")                                                       \
        for (int kk = 0; kk < 4; kk++) {                                        \
            uint32_t afr[4][4];                                                 \
            _Pragma("unroll")                                                   \
            for (int mi = 0; mi < 4; mi++) {                                    \
                int row = wm + mi * 16 + a_row_lane;                            \
                uint32_t off = (uint32_t)(row * 128 + kk * 32 + a_col_lane);    \
                LDSM_X4(afr[mi], sA + SW(off));                                 \
            }                                                                   \
            uint32_t bfr[2][4];                                                 \
            _Pragma("unroll")                                                   \
            for (int nj = 0; nj < 2; nj++) {                                    \
                int row = wn + nj * 16 + b_row_lane;                            \
                uint32_t off = (uint32_t)(row * 128 + kk * 32 + b_col_lane);    \
                LDSM_X4(bfr[nj], sB + SW(off));                                 \
            }                                                                   \
            _Pragma("unroll")                                                   \
            for (int mi = 0; mi < 4; mi++) {                                    \
                _Pragma("unroll")                                               \
                for (int ni = 0; ni < 4; ni++) {                                \
                    const uint32_t b0 = bfr[ni >> 1][(ni & 1) * 2 + 0];         \
                    const uint32_t b1 = bfr[ni >> 1][(ni & 1) * 2 + 1];         \
                    MMA16816(acc[mi][ni], afr[mi], b0, b1);                     \
                }                                                               \
            }                                                                   \
        }                                                                       \
    }

    // prologue: fill STAGES-1 stages
    ISSUE_STAGE(0, 0); CP_COMMIT();
    ISSUE_STAGE(1, 1); CP_COMMIT();

    // main loop: 21 x 3 = kt 0..62, stage index static per sub-iteration
    for (int kt0 = 0; kt0 < NKT - 1; kt0 += STAGES) {
        KT_BODY(0, kt0 + 0);
        KT_BODY(1, kt0 + 1);
        KT_BODY(2, kt0 + 2);
    }
    // tail: kt = 63 (63 % 3 == 0)
    KT_BODY(0, NKT - 1);

    // ---- epilogue: direct float2 stores
    float* ob = out + (size_t)b * MDIM * NB;
    const int cr = lane >> 2;
    const int ccol = (lane & 3) * 2;
    #pragma unroll
    for (int mi = 0; mi < 4; mi++) {
        #pragma unroll
        for (int ni = 0; ni < 4; ni++) {
            int r0 = m0 + wm + mi * 16 + cr;
            int c  = n0 + wn + ni * 8 + ccol;
            float2 v0 = make_float2(acc[mi][ni][0], acc[mi][ni][1]);
            float2 v1 = make_float2(acc[mi][ni][2], acc[mi][ni][3]);
            *reinterpret_cast<float2*>(ob + (size_t)r0 * NB + c)       = v0;
            *reinterpret_cast<float2*>(ob + (size_t)(r0 + 8) * NB + c) = v1;
        }
    }
}

// ---------------------------------------------------------------------------
// Host launch (graph-capturable). Pre-pass forked across two streams:
//   main:  fused zero+scatter ----\
//   side:  convert_x -------------+--> gemm
// ---------------------------------------------------------------------------
extern "C" void kernel_launch(void* const* d_in, const int* in_sizes, int n_in,
                              void* d_out, int out_size) {
    const float* x    = (const float*)d_in[0];
    const float* vals = (const float*)d_in[1];
    const int*   ci   = (const int*)d_in[3];
    float* out = (float*)d_out;
    int nnz = in_sizes[1];
    int m   = in_sizes[2] - 1;
    int per_row = nnz / m;

    static cudaStream_t s2 = nullptr;
    static cudaEvent_t evFork = nullptr, evJoin = nullptr;
    static bool init_done = false;
    if (!init_done) {
        cudaFuncSetAttribute(gemm_kernel,
                             cudaFuncAttributeMaxDynamicSharedMemorySize,
                             SMEM_TOTAL);
        cudaStreamCreateWithFlags(&s2, cudaStreamNonBlocking);
        cudaEventCreateWithFlags(&evFork, cudaEventDisableTiming);
        cudaEventCreateWithFlags(&evJoin, cudaEventDisableTiming);
        init_done = true;
    }

    // fork: side stream does x conversion concurrently with scatter
    cudaEventRecord(evFork, 0);
    cudaStreamWaitEvent(s2, evFork, 0);
    convert_x_kernel<<<(int)(((size_t)NTOT * KDIM / 8) / 256), 256, 0, s2>>>(
        (const float4*)x);
    cudaEventRecord(evJoin, s2);

    // main stream: fused zero + scatter (no separate memset)
    scatter_fused_kernel<<<m, 256>>>(vals, ci, per_row);

    // join, then GEMM
    cudaStreamWaitEvent(0, evJoin, 0);
    dim3 grid(NB / BN, MDIM / BM, BDIM);
    gemm_kernel<<<grid, THREADS, SMEM_TOTAL>>>(out);
}

// round 16
// speedup vs baseline: 1.5125x; 1.5125x over previous
#include <cuda_runtime.h>
#include <cuda_fp16.h>
#include <cstdint>

// Problem shape (fixed)
#define MDIM 4096
#define KDIM 4096
#define BDIM 4
#define NB   2048
#define NTOT (BDIM * NB)   // 8192

// GEMM tiling: 128x128x64, 256 threads, 3 stages, 2 CTAs/SM (R6 winner)
#define BM 128
#define BN 128
#define BK 64              // 64 fp16 = 128B row
#define STAGES 3
#define NKT (KDIM / BK)    // 64
#define THREADS 256

#define A_SZ (BM * BK * 2)             // 16384 B
#define B_SZ (BN * BK * 2)             // 16384 B
#define STAGE_SZ (A_SZ + B_SZ)         // 32768 B
#define SMEM_TOTAL (STAGES * STAGE_SZ) // 98304 B -> 2 CTAs/SM

// SW128-style swizzle for 128B rows (XOR bits[6:4] with bits[9:7])
#define SW(o) ((o) ^ (((o) >> 3) & 0x70))

// Scratch (device globals — no allocation allowed)
__device__ __align__(1024) __half g_Wh[(size_t)MDIM * KDIM];   // 33.5 MB dense W fp16
__device__ __align__(1024) __half g_xh[(size_t)NTOT * KDIM];   // 67 MB x fp16

// ---------------------------------------------------------------------------
// PTX helpers (baseline sm_80/sm_90 features only)
// ---------------------------------------------------------------------------
__device__ __forceinline__ uint32_t smem_u32(const void* p) {
    uint32_t a;
    asm("{ .reg .u64 t; cvta.to.shared.u64 t, %1; cvt.u32.u64 %0, t; }"
        : "=r"(a) : "l"(p));
    return a;
}

__device__ __forceinline__ void cp_async16(uint32_t dst, const void* src) {
    asm volatile("cp.async.cg.shared.global [%0], [%1], 16;"
                 :: "r"(dst), "l"(src) : "memory");
}
#define CP_COMMIT() asm volatile("cp.async.commit_group;" ::: "memory")
#define CP_WAIT(n)  asm volatile("cp.async.wait_group %0;" :: "n"(n) : "memory")

#define LDSM_X4(R, addr) \
    asm volatile("ldmatrix.sync.aligned.m8n8.x4.shared.b16 {%0,%1,%2,%3}, [%4];" \
                 : "=r"((R)[0]), "=r"((R)[1]), "=r"((R)[2]), "=r"((R)[3]) \
                 : "r"(addr))

#define MMA16816(d, a, b0, b1) \
    asm volatile("mma.sync.aligned.m16n8k16.row.col.f32.f16.f16.f32 " \
                 "{%0,%1,%2,%3}, {%4,%5,%6,%7}, {%8,%9}, {%0,%1,%2,%3};" \
                 : "+f"((d)[0]), "+f"((d)[1]), "+f"((d)[2]), "+f"((d)[3]) \
                 : "r"((a)[0]), "r"((a)[1]), "r"((a)[2]), "r"((a)[3]), \
                   "r"(b0), "r"(b1))

// ---------------------------------------------------------------------------
// Kernel 1: deterministic CSR -> dense fp16 scatter (no atomics)
// Uniform CSR (nnz/m per row); cols sorted per row, duplicate runs adjacent.
// ---------------------------------------------------------------------------
__global__ void scatter_w_kernel(const float* __restrict__ vals,
                                 const int* __restrict__ ci,
                                 int nnz, int m) {
    int j = blockIdx.x * blockDim.x + threadIdx.x;
    if (j >= nnz) return;
    const int per_row = nnz / m;
    int row = j / per_row;
    int rs = row * per_row, re = rs + per_row;
    int c = ci[j];
    if (j > rs && ci[j - 1] == c) return; // not run head
    float s = vals[j];
    int t = j + 1;
    while (t < re && ci[t] == c) { s += vals[t]; t++; }
    g_Wh[(size_t)row * KDIM + c] = __float2half_rn(s);
}

// ---------------------------------------------------------------------------
// Kernel 2: x fp32 -> fp16 (8 floats / thread, 16B stores)
// ---------------------------------------------------------------------------
__global__ void convert_x_kernel(const float4* __restrict__ x) {
    size_t i = (size_t)blockIdx.x * blockDim.x + threadIdx.x;
    float4 a = x[2 * i];
    float4 b = x[2 * i + 1];
    __half2 h0 = __floats2half2_rn(a.x, a.y);
    __half2 h1 = __floats2half2_rn(a.z, a.w);
    __half2 h2 = __floats2half2_rn(b.x, b.y);
    __half2 h3 = __floats2half2_rn(b.z, b.w);
    uint4 o;
    o.x = *reinterpret_cast<uint32_t*>(&h0);
    o.y = *reinterpret_cast<uint32_t*>(&h1);
    o.z = *reinterpret_cast<uint32_t*>(&h2);
    o.w = *reinterpret_cast<uint32_t*>(&h3);
    reinterpret_cast<uint4*>(g_xh)[i] = o;
}

// ---------------------------------------------------------------------------
// Kernel 3: fp16 GEMM via mma.sync (HMMA), 128x128x64 tiles, 3-stage cp.async,
// 2 CTAs/SM, kt-loop unrolled by STAGES for static stage addressing.
// C[m, gn] = sum_k Wh[m,k] * xh[gn,k]
// ---------------------------------------------------------------------------
__global__ __launch_bounds__(THREADS, 2)
void gemm_kernel(float* __restrict__ out) {
    extern __shared__ __align__(1024) char smem[];
    const uint32_t sb = smem_u32(smem);
    const int tid = threadIdx.x;
    const int wid = tid >> 5;
    const int lane = tid & 31;

    const int n0 = blockIdx.x * BN;       // n within batch
    const int m0 = blockIdx.y * BM;
    const int b  = blockIdx.z;

    const __half* gA = g_Wh + (size_t)m0 * KDIM;                 // [BM, K]
    const __half* gB = g_xh + ((size_t)b * NB + n0) * KDIM;      // [BN, K]

    // warp layout: 2 (m) x 4 (n); warp tile 64 x 32
    const int wm = (wid & 1) * 64;
    const int wn = (wid >> 1) * 32;

    float acc[4][4][4];
    #pragma unroll
    for (int i = 0; i < 4; i++)
        #pragma unroll
        for (int j = 0; j < 4; j++)
            #pragma unroll
            for (int q = 0; q < 4; q++) acc[i][j][q] = 0.f;

    // loader thread's fixed chunk coords (row r, 16B-chunk cc within 128B row)
    const int ld_r0 = tid >> 3;          // rows 0..31 (+32 per j)
    const int ld_cc = (tid & 7) * 16;    // byte offset of 16B chunk

    // ---- stage loader: 8 x cp.async16 per thread (A:4, B:4), stage s static
    #define ISSUE_STAGE(S, KT)                                                  \
    {                                                                           \
        const uint32_t sA_ = sb + (S) * STAGE_SZ;                               \
        const uint32_t sB_ = sA_ + A_SZ;                                        \
        const __half* ga_ = gA + (KT) * BK;                                     \
        const __half* gb_ = gB + (KT) * BK;                                     \
        _Pragma("unroll")                                                       \
        for (int j = 0; j < 4; j++) {                                           \
            int r = ld_r0 + j * 32;                                             \
            cp_async16(sA_ + SW(r * 128 + ld_cc),                               \
                       ga_ + (size_t)r * KDIM + (ld_cc >> 1));                  \
            cp_async16(sB_ + SW(r * 128 + ld_cc),                               \
                       gb_ + (size_t)r * KDIM + (ld_cc >> 1));                  \
        }                                                                       \
    }

    // ldmatrix lane address components
    const int a_row_lane = lane & 15;                       // A: row within m16
    const int a_col_lane = (lane >> 4) << 4;                // A: 0 or 16 bytes
    const int b_row_lane = ((lane >> 4) << 3) + (lane & 7); // B: row within n16
    const int b_col_lane = ((lane >> 3) & 1) << 4;          // B: 0 or 16 bytes

    // ---- one kt step with compile-time stage S
    #define KT_BODY(S, KT)                                                      \
    {                                                                           \
        CP_WAIT(STAGES - 2);                                                    \
        __syncthreads();                                                        \
        if ((KT) + STAGES - 1 < NKT) ISSUE_STAGE(((S) + STAGES - 1) % STAGES,   \
                                                 (KT) + STAGES - 1);            \
        CP_COMMIT();                                                            \
        const uint32_t sA = sb + (S) * STAGE_SZ;                                \
        const uint32_t sB = sA + A_SZ;                                          \
        _Pragma("unroll")                                                       \
        for (int kk = 0; kk < 4; kk++) {                                        \
            uint32_t afr[4][4];                                                 \
            _Pragma("unroll")                                                   \
            for (int mi = 0; mi < 4; mi++) {                                    \
                int row = wm + mi * 16 + a_row_lane;                            \
                uint32_t off = (uint32_t)(row * 128 + kk * 32 + a_col_lane);    \
                LDSM_X4(afr[mi], sA + SW(off));                                 \
            }                                                                   \
            uint32_t bfr[2][4];                                                 \
            _Pragma("unroll")                                                   \
            for (int nj = 0; nj < 2; nj++) {                                    \
                int row = wn + nj * 16 + b_row_lane;                            \
                uint32_t off = (uint32_t)(row * 128 + kk * 32 + b_col_lane);    \
                LDSM_X4(bfr[nj], sB + SW(off));                                 \
            }                                                                   \
            _Pragma("unroll")                                                   \
            for (int mi = 0; mi < 4; mi++) {                                    \
                _Pragma("unroll")                                               \
                for (int ni = 0; ni < 4; ni++) {                                \
                    const uint32_t b0 = bfr[ni >> 1][(ni & 1) * 2 + 0];         \
                    const uint32_t b1 = bfr[ni >> 1][(ni & 1) * 2 + 1];         \
                    MMA16816(acc[mi][ni], afr[mi], b0, b1);                     \
                }                                                               \
            }                                                                   \
        }                                                                       \
    }

    // prologue: fill STAGES-1 stages
    ISSUE_STAGE(0, 0); CP_COMMIT();
    ISSUE_STAGE(1, 1); CP_COMMIT();

    // main loop: 21 x 3 = kt 0..62, stage index static per sub-iteration
    for (int kt0 = 0; kt0 < NKT - 1; kt0 += STAGES) {
        KT_BODY(0, kt0 + 0);
        KT_BODY(1, kt0 + 1);
        KT_BODY(2, kt0 + 2);
    }
    // tail: kt = 63 (63 % 3 == 0)
    KT_BODY(0, NKT - 1);

    // ---- epilogue: direct float2 stores
    float* ob = out + (size_t)b * MDIM * NB;
    const int cr = lane >> 2;
    const int ccol = (lane & 3) * 2;
    #pragma unroll
    for (int mi = 0; mi < 4; mi++) {
        #pragma unroll
        for (int ni = 0; ni < 4; ni++) {
            int r0 = m0 + wm + mi * 16 + cr;
            int c  = n0 + wn + ni * 8 + ccol;
            float2 v0 = make_float2(acc[mi][ni][0], acc[mi][ni][1]);
            float2 v1 = make_float2(acc[mi][ni][2], acc[mi][ni][3]);
            *reinterpret_cast<float2*>(ob + (size_t)r0 * NB + c)       = v0;
            *reinterpret_cast<float2*>(ob + (size_t)(r0 + 8) * NB + c) = v1;
        }
    }
}

// ---------------------------------------------------------------------------
// Host launch (graph-capturable). Pre-pass forked across two streams:
//   main:  memset(W) -> scatter ----\
//   side:  convert_x ---------------+--> gemm
// ---------------------------------------------------------------------------
extern "C" void kernel_launch(void* const* d_in, const int* in_sizes, int n_in,
                              void* d_out, int out_size) {
    const float* x    = (const float*)d_in[0];
    const float* vals = (const float*)d_in[1];
    const int*   ci   = (const int*)d_in[3];
    float* out = (float*)d_out;
    int nnz = in_sizes[1];
    int m   = in_sizes[2] - 1;

    void* whPtr = nullptr;
    cudaGetSymbolAddress(&whPtr, g_Wh);

    static cudaStream_t s2 = nullptr;
    static cudaEvent_t evFork = nullptr, evJoin = nullptr;
    static bool init_done = false;
    if (!init_done) {
        cudaFuncSetAttribute(gemm_kernel,
                             cudaFuncAttributeMaxDynamicSharedMemorySize,
                             SMEM_TOTAL);
        cudaStreamCreateWithFlags(&s2, cudaStreamNonBlocking);
        cudaEventCreateWithFlags(&evFork, cudaEventDisableTiming);
        cudaEventCreateWithFlags(&evJoin, cudaEventDisableTiming);
        init_done = true;
    }

    // fork: side stream does x conversion concurrently with memset+scatter
    cudaEventRecord(evFork, 0);
    cudaStreamWaitEvent(s2, evFork, 0);
    convert_x_kernel<<<(int)(((size_t)NTOT * KDIM / 8) / 256), 256, 0, s2>>>(
        (const float4*)x);
    cudaEventRecord(evJoin, s2);

    // main stream: zero W, then scatter CSR -> dense fp16
    cudaMemsetAsync(whPtr, 0, (size_t)MDIM * KDIM * sizeof(__half), 0);
    scatter_w_kernel<<<(nnz + 255) / 256, 256>>>(vals, ci, nnz, m);

    // join, then GEMM
    cudaStreamWaitEvent(0, evJoin, 0);
    dim3 grid(NB / BN, MDIM / BM, BDIM);
    gemm_kernel<<<grid, THREADS, SMEM_TOTAL>>>(out);
}